// round 7
// baseline (speedup 1.0000x reference)
#include <cuda_runtime.h>

// Stochastic LIF neuron scan — R6.
// Inputs (metadata order): x [B,T,N] f32, noise [B,T,N] f32, unif [B,T,N] f32.
// Output: spikes [B,T,N] f32.
//
// Per (b,n):  u=0
//   u = 0.5*u + x_t        (separate mul+add, NO fma — matches JAX rounding)
//   u = u - noise_t
//   v = u - 1
//   q = (v + 0.4) / 0.8    (IEEE f32 division; clip removed — bit-identical
//                           since unif ∈ [0,1))
//   o = (unif_t < q) ? 1 : 0
//   u = o ? 0 : u
//
// R6 change (single variable vs R5): fully unroll the T=16 scan with
// compile-time offsets. The only loop-carried state is the 4 membrane floats,
// so ptxas can hoist the next timestep's 3 LDG.128 well ahead of the current
// timestep's short mul/add/div chain -> higher MLP_eff, the last movable term
// in the DRAM-bound cycle model. Loop index math and branch disappear.

#define B_DIM 32
#define T_DIM 16
#define N_DIM 65536
#define N4    (N_DIM / 4)   // 16384 float4 per (b,t) row

struct U4 { float u0, u1, u2, u3; };

__device__ __forceinline__ void lif_lane(float& u, float xv, float nv, float rv,
                                         float& ov)
{
    float un = __fadd_rn(__fmul_rn(0.5f, u), xv);
    un = __fsub_rn(un, nv);
    float v = __fsub_rn(un, 1.0f);
    float q = __fdiv_rn(__fadd_rn(v, 0.4f), 0.8f);
    bool  s = (rv < q);
    ov = s ? 1.0f : 0.0f;
    u  = s ? 0.0f : un;
}

__global__ __launch_bounds__(256)
void neuron_scan_kernel(const float4* __restrict__ x,
                        const float4* __restrict__ noise,
                        const float4* __restrict__ unif,
                        float4* __restrict__ out)
{
    int tid = blockIdx.x * blockDim.x + threadIdx.x;   // 0 .. B*N4-1 (grid exact)

    int b  = tid >> 14;          // tid / N4
    int n4 = tid & (N4 - 1);     // tid % N4

    // element-of-float4 index of (b, t=0, n4)
    int base = b * (T_DIM * N4) + n4;

    float u0 = 0.0f, u1 = 0.0f, u2 = 0.0f, u3 = 0.0f;

    #pragma unroll
    for (int t = 0; t < T_DIM; ++t) {
        int idx = base + t * N4;   // t is compile-time -> immediate offsets

        float4 xv = x[idx];
        float4 nv = noise[idx];
        float4 rv = unif[idx];

        float4 ov;
        lif_lane(u0, xv.x, nv.x, rv.x, ov.x);
        lif_lane(u1, xv.y, nv.y, rv.y, ov.y);
        lif_lane(u2, xv.z, nv.z, rv.z, ov.z);
        lif_lane(u3, xv.w, nv.w, rv.w, ov.w);

        out[idx] = ov;
    }
}

extern "C" void kernel_launch(void* const* d_in, const int* in_sizes, int n_in,
                              void* d_out, int out_size)
{
    const float4* x     = (const float4*)d_in[0];
    const float4* noise = (const float4*)d_in[1];
    const float4* unif  = (const float4*)d_in[2];
    float4* out         = (float4*)d_out;

    const int total_threads = B_DIM * N4;          // 524288
    const int block = 256;
    const int grid  = total_threads / block;       // 2048, exact

    neuron_scan_kernel<<<grid, block>>>(x, noise, unif, out);
}

// round 8
// speedup vs baseline: 1.0514x; 1.0514x over previous
#include <cuda_runtime.h>

// Stochastic LIF neuron scan — R7.
// Inputs (metadata order): x [B,T,N] f32, noise [B,T,N] f32, unif [B,T,N] f32.
// Output: spikes [B,T,N] f32.
//
// Bit-exact step per (b,n):
//   u = 0.5*u + x_t        (separate mul+add, NO fma)
//   u = u - noise_t
//   q = ((u - 1) + 0.4) / 0.8   (IEEE div; clip elided — unif ∈ [0,1))
//   o = (unif_t < q);  u = o ? 0 : u
//
// R7 change vs R5 (best, 82.66us): 2 float4 tiles per thread (8 elems over n),
// grid 1024. Measured pattern R3-R6: fewer co-resident CTAs/SM -> higher DRAM%
// (cross-CTA L1tex queue contention). This halves CTA count while doubling
// per-warp loads in flight; unroll-4 over t and default cache ops retained.

#define B_DIM 32
#define T_DIM 16
#define N_DIM 65536
#define N4    (N_DIM / 4)     // 16384 float4 per (b,t) row
#define HALF  (N4 / 2)        // 8192: second tile offset within a row

__device__ __forceinline__ void lif_lane(float& u, float xv, float nv, float rv,
                                         float& ov)
{
    float un = __fadd_rn(__fmul_rn(0.5f, u), xv);
    un = __fsub_rn(un, nv);
    float v = __fsub_rn(un, 1.0f);
    float q = __fdiv_rn(__fadd_rn(v, 0.4f), 0.8f);
    bool  s = (rv < q);
    ov = s ? 1.0f : 0.0f;
    u  = s ? 0.0f : un;
}

__global__ __launch_bounds__(256)
void neuron_scan_kernel(const float4* __restrict__ x,
                        const float4* __restrict__ noise,
                        const float4* __restrict__ unif,
                        float4* __restrict__ out)
{
    int tid = blockIdx.x * blockDim.x + threadIdx.x;   // 0 .. B*HALF-1 (grid exact)

    int b   = tid >> 13;            // tid / HALF
    int off = tid & (HALF - 1);     // tid % HALF

    // two float4 tiles per thread: columns off and off+HALF of each row
    int idxA = b * (T_DIM * N4) + off;
    int idxB = idxA + HALF;

    float a0 = 0.0f, a1 = 0.0f, a2 = 0.0f, a3 = 0.0f;
    float b0 = 0.0f, b1 = 0.0f, b2 = 0.0f, b3 = 0.0f;

    #pragma unroll 4
    for (int t = 0; t < T_DIM; ++t) {
        float4 xa = x[idxA];
        float4 xb = x[idxB];
        float4 na = noise[idxA];
        float4 nb = noise[idxB];
        float4 ra = unif[idxA];
        float4 rb = unif[idxB];

        float4 oa, ob;
        lif_lane(a0, xa.x, na.x, ra.x, oa.x);
        lif_lane(a1, xa.y, na.y, ra.y, oa.y);
        lif_lane(a2, xa.z, na.z, ra.z, oa.z);
        lif_lane(a3, xa.w, na.w, ra.w, oa.w);

        lif_lane(b0, xb.x, nb.x, rb.x, ob.x);
        lif_lane(b1, xb.y, nb.y, rb.y, ob.y);
        lif_lane(b2, xb.z, nb.z, rb.z, ob.z);
        lif_lane(b3, xb.w, nb.w, rb.w, ob.w);

        out[idxA] = oa;
        out[idxB] = ob;

        idxA += N4;
        idxB += N4;
    }
}

extern "C" void kernel_launch(void* const* d_in, const int* in_sizes, int n_in,
                              void* d_out, int out_size)
{
    const float4* x     = (const float4*)d_in[0];
    const float4* noise = (const float4*)d_in[1];
    const float4* unif  = (const float4*)d_in[2];
    float4* out         = (float4*)d_out;

    const int total_threads = B_DIM * HALF;        // 262144
    const int block = 256;
    const int grid  = total_threads / block;       // 1024, exact

    neuron_scan_kernel<<<grid, block>>>(x, noise, unif, out);
}